// round 15
// baseline (speedup 1.0000x reference)
#include <cuda_runtime.h>
#include <cuda_bf16.h>
#include <cstdint>
#include <cstddef>

// Problem constants
#define Bb   16
#define Nn   4096
#define Dd   256
#define Kk   512
#define ROWS (Bb * Nn)        // 65536
#define TMm  128              // rows per MMA CTA
#define NBLK (ROWS / TMm)     // 512
#define DELTA 0.5f

// smem layout (bytes): A-hi resident (4 x 16KB d-chunk tiles), B hi/lo chunk, esq, reduce
#define OFF_AH  0
#define OFF_BH  (64 * 1024)
#define OFF_BL  (80 * 1024)
#define OFF_ESQ (96 * 1024)           // 512 floats
#define OFF_RB1 (OFF_ESQ + 2048)      // float sb1[128][2]
#define OFF_RK1 (OFF_RB1 + 1024)      // int   sk1[128][2]
#define OFF_RB2 (OFF_RK1 + 1024)      // float sb2[128][2]
#define SMEM_SZ (OFF_RB2 + 1024 + 32) // ~101.1 KB -> 2 CTAs/SM

// ---------------- device globals (zero-init; reset_k restores at replay end) ----------------
__device__ double g_loss;
__device__ int    g_mflag;
__device__ int    g_nflag;
__device__ float  g_esq[Kk];
__device__ int    g_bestk[ROWS];
__device__ int    g_flaglist[ROWS];
__device__ uint4  g_cbh4[Kk * Dd / 8];    // codebook hi bf16 [code][dim/8] (256KB)
__device__ uint4  g_cbl4[Kk * Dd / 8];    // codebook lo bf16 (256KB)
__device__ uint4  g_zh4[ROWS * Dd / 8];   // z hi bf16 [row][dim/8] (32MB)

// ---------------- helpers ----------------
__device__ __forceinline__ uint32_t smem_u32(const void* p) {
    uint32_t a;
    asm("{ .reg .u64 t; cvta.to.shared.u64 t, %1; cvt.u32.u64 %0, t; }" : "=r"(a) : "l"(p));
    return a;
}

#define LDSM4(r, addr)                                                              \
    asm volatile("ldmatrix.sync.aligned.m8n8.x4.shared.b16 {%0,%1,%2,%3}, [%4];"    \
        : "=r"((r)[0]), "=r"((r)[1]), "=r"((r)[2]), "=r"((r)[3]) : "r"(addr))

#define MMA16816(c, a, b0, b1)                                                      \
    asm volatile("mma.sync.aligned.m16n8k16.row.col.f32.bf16.bf16.f32 "             \
        "{%0,%1,%2,%3}, {%4,%5,%6,%7}, {%8,%9}, {%0,%1,%2,%3};"                     \
        : "+f"((c)[0]), "+f"((c)[1]), "+f"((c)[2]), "+f"((c)[3])                    \
        : "r"((a)[0]), "r"((a)[1]), "r"((a)[2]), "r"((a)[3]), "r"(b0), "r"(b1))

// packed hi-only: 8 floats -> uint4 of bf16(v) pairs (4 cvt insts)
__device__ __forceinline__ uint4 pack_hi8(const float* v) {
    uint32_t w[4];
#pragma unroll
    for (int j = 0; j < 4; ++j)
        asm("cvt.rn.bf16x2.f32 %0, %1, %2;" : "=r"(w[j]) : "f"(v[2 * j + 1]), "f"(v[2 * j]));
    return make_uint4(w[0], w[1], w[2], w[3]);
}

// packed full split: 8 floats -> hi uint4 + lo uint4 (8 cvt insts)
__device__ __forceinline__ void split8_fast(const float* v, uint4& h, uint4& l) {
    uint32_t hw[4], lw[4];
#pragma unroll
    for (int j = 0; j < 4; ++j)
        asm("cvt.rn.bf16x2.f32 %0, %1, %2;" : "=r"(hw[j]) : "f"(v[2 * j + 1]), "f"(v[2 * j]));
#pragma unroll
    for (int j = 0; j < 4; ++j) {
        float h0 = __int_as_float(hw[j] << 16);
        float h1 = __int_as_float(hw[j] & 0xFFFF0000u);
        float l0 = v[2 * j]     - h0;
        float l1 = v[2 * j + 1] - h1;
        asm("cvt.rn.bf16x2.f32 %0, %1, %2;" : "=r"(lw[j]) : "f"(l1), "f"(l0));
    }
    h = make_uint4(hw[0], hw[1], hw[2], hw[3]);
    l = make_uint4(lw[0], lw[1], lw[2], lw[3]);
}

// merge (b1,k1,b2) with (ob1,ok1,ob2); argmin tie-break = lowest index
__device__ __forceinline__ void merge2(float& b1, int& k1, float& b2,
                                       float ob1, int ok1, float ob2) {
    float lose;
    if (ob1 < b1 || (ob1 == b1 && ok1 < k1)) { lose = b1; b1 = ob1; k1 = ok1; }
    else lose = ob1;
    b2 = fminf(b2, fminf(ob2, lose));
}

__device__ __forceinline__ int read_mask(const void* m, int n, int flag) {
    if (flag & 2) return ((const float*)m)[n] != 0.0f;
    if (flag & 1) return ((const unsigned char*)m)[n] != 0;
    return ((const int*)m)[n] != 0;
}

// ---------------- prologue kernels ----------------
__global__ void detect_k(const unsigned int* __restrict__ m) {
    int i = blockIdx.x * blockDim.x + threadIdx.x;
    int flags = 0;
    for (int idx = i; idx < (ROWS / 4); idx += gridDim.x * blockDim.x) {
        unsigned int v = m[idx];
        if (v == 0x3F800000u) flags |= 2;
        else if (v > 1u)      flags |= 1;
    }
    if (flags) atomicOr(&g_mflag, flags);
}

// codebook -> bf16 hi/lo packs + ||e||^2. grid 64, block 256 (warp per code).
__global__ void prep_cb(const float* __restrict__ cb) {
    int w    = threadIdx.x >> 5;
    int lane = threadIdx.x & 31;
    int code = blockIdx.x * 8 + w;
    float v[8];
    const float* p = cb + (size_t)code * Dd + lane * 8;
#pragma unroll
    for (int j = 0; j < 8; ++j) v[j] = p[j];
    uint4 h, l;
    split8_fast(v, h, l);
    g_cbh4[code * 32 + lane] = h;
    g_cbl4[code * 32 + lane] = l;
    float s = 0.f;
#pragma unroll
    for (int j = 0; j < 8; ++j) s = fmaf(v[j], v[j], s);
#pragma unroll
    for (int off = 16; off > 0; off >>= 1) s += __shfl_down_sync(0xFFFFFFFFu, s, off);
    if (lane == 0) g_esq[code] = s;
}

// z -> bf16 hi packs. grid 8192, block 256.
__global__ void prep_z(const float* __restrict__ z) {
    int idx = blockIdx.x * 256 + threadIdx.x;       // 0..2M-1
    float v[8];
    const float* p = z + (size_t)idx * 8;
    const float4 v0 = *reinterpret_cast<const float4*>(p);
    const float4 v1 = *reinterpret_cast<const float4*>(p + 4);
    v[0] = v0.x; v[1] = v0.y; v[2] = v0.z; v[3] = v0.w;
    v[4] = v1.x; v[5] = v1.y; v[6] = v1.z; v[7] = v1.w;
    g_zh4[idx] = pack_hi8(v);
}

// ---------------- main MMA kernel (R10 verbatim: best-measured 117us) ----------------
// CTA: 128 rows x 512 codes (4 chunks of 128), K=256. A-hi resident (streamed from
// presplit g_zh4); B hi/lo streamed. 8 warps 4(m)x2(n); mma.m16n8k16 bf16.
// A = z_hi only; B = e_hi + e_lo. Error covered by DELTA + rescue.
__global__ __launch_bounds__(256, 2) void vq_mma() {
    extern __shared__ char smem[];
    const uint32_t sb = smem_u32(smem);
    const int tid  = threadIdx.x;
    const int lane = tid & 31;
    const int wid  = tid >> 5;
    const int wm   = wid >> 1;         // 0..3
    const int wn   = wid & 1;          // 0..1
    const int g    = lane >> 2;        // 0..7
    const int tg   = lane & 3;         // 0..3
    const int r0   = blockIdx.x * TMm;

    float* esq_s = (float*)(smem + OFF_ESQ);
    esq_s[tid]       = g_esq[tid];
    esq_s[tid + 256] = g_esq[tid + 256];

    // ---- fill A-hi once: 4 d-chunk tiles of [128 rows][64 dims] SW128 ----
#pragma unroll
    for (int it = 0; it < 16; ++it) {
        int idx = tid + it * 256;          // 0..4095
        int row = idx >> 5;                // 0..127
        int u   = idx & 31;                // uint4 within row (8 dims)
        int dc  = u >> 3;
        int q   = u & 7;
        uint32_t off = dc * 16384 + row * 128 + ((q * 16) ^ ((row & 7) * 16));
        *reinterpret_cast<uint4*>(smem + OFF_AH + off) = g_zh4[(r0 + row) * 32 + u];
    }

    // ldmatrix per-lane constants
    const int sw      = (lane & 7) * 16;
    const int aRowT   = ((lane >> 3) & 1) * 8 + (lane & 7);
    const int aByteT  = (lane >> 4) * 16;
    const int bCodeT  = (lane >> 4) * 8 + (lane & 7);
    const int bByteT  = ((lane >> 3) & 1) * 16;

    float bs1[4], bs2[4];
    int   bk1[4];
#pragma unroll
    for (int s = 0; s < 4; ++s) { bs1[s] = 3.4e38f; bs2[s] = 3.4e38f; bk1[s] = 0; }

    for (int kc = 0; kc < 4; ++kc) {               // code chunks of 128
        float acc[2][8][4];
#pragma unroll
        for (int mt = 0; mt < 2; ++mt)
#pragma unroll
            for (int nt = 0; nt < 8; ++nt)
#pragma unroll
                for (int c = 0; c < 4; ++c) acc[mt][nt][c] = 0.f;

        for (int dc = 0; dc < 4; ++dc) {           // d chunks of 64
            __syncthreads();
            // ---- fill B chunk hi/lo: [128 codes][64 dims] SW128 ----
#pragma unroll
            for (int it = 0; it < 4; ++it) {
                int idx  = tid + it * 256;
                int code = idx >> 3;
                int q    = idx & 7;
                int gi   = (kc * 128 + code) * 32 + dc * 8 + q;
                uint32_t off = code * 128 + ((q * 16) ^ ((code & 7) * 16));
                *reinterpret_cast<uint4*>(smem + OFF_BH + off) = g_cbh4[gi];
                *reinterpret_cast<uint4*>(smem + OFF_BL + off) = g_cbl4[gi];
            }
            __syncthreads();

            const uint32_t aBase = sb + OFF_AH + dc * 16384 +
                                   (uint32_t)((wm * 32 + aRowT) * 128);
            const uint32_t bBase = sb + OFF_BH + (uint32_t)((wn * 64 + bCodeT) * 128);

#pragma unroll
            for (int ks = 0; ks < 4; ++ks) {       // K16 steps
                const uint32_t xa = (uint32_t)((ks * 32 + aByteT) ^ sw);
                const uint32_t xb = (uint32_t)((ks * 32 + bByteT) ^ sw);

                uint32_t ah[2][4];
#pragma unroll
                for (int mt = 0; mt < 2; ++mt)
                    LDSM4(ah[mt], aBase + mt * (16 * 128) + xa);
                uint32_t bh[4][4], bl[4][4];
#pragma unroll
                for (int np = 0; np < 4; ++np) {
                    LDSM4(bh[np], bBase + np * (16 * 128) + xb);
                    LDSM4(bl[np], bBase + (OFF_BL - OFF_BH) + np * (16 * 128) + xb);
                }
#pragma unroll
                for (int mt = 0; mt < 2; ++mt)
#pragma unroll
                    for (int np = 0; np < 4; ++np) {
                        MMA16816(acc[mt][2 * np],     ah[mt], bh[np][0], bh[np][1]);
                        MMA16816(acc[mt][2 * np],     ah[mt], bl[np][0], bl[np][1]);
                        MMA16816(acc[mt][2 * np + 1], ah[mt], bh[np][2], bh[np][3]);
                        MMA16816(acc[mt][2 * np + 1], ah[mt], bl[np][2], bl[np][3]);
                    }
            }
        }

        // ---- fold chunk into running argmin: score = esq - 2*dot ----
        const int ccbase = kc * 128 + wn * 64;
#pragma unroll
        for (int mt = 0; mt < 2; ++mt)
#pragma unroll
            for (int nt = 0; nt < 8; ++nt)
#pragma unroll
                for (int c = 0; c < 4; ++c) {
                    int code = ccbase + nt * 8 + 2 * tg + (c & 1);
                    int slot = mt * 2 + (c >> 1);
                    float s = fmaf(-2.f, acc[mt][nt][c], esq_s[code]);
                    if (s < bs1[slot]) { bs2[slot] = bs1[slot]; bs1[slot] = s; bk1[slot] = code; }
                    else if (s < bs2[slot]) bs2[slot] = s;
                }
    }

    // ---- quad reduce ----
#pragma unroll
    for (int s = 0; s < 4; ++s) {
#pragma unroll
        for (int m = 1; m <= 2; m <<= 1) {
            float ob1 = __shfl_xor_sync(0xFFFFFFFFu, bs1[s], m);
            int   ok1 = __shfl_xor_sync(0xFFFFFFFFu, bk1[s], m);
            float ob2 = __shfl_xor_sync(0xFFFFFFFFu, bs2[s], m);
            merge2(bs1[s], bk1[s], bs2[s], ob1, ok1, ob2);
        }
    }
    __syncthreads();
    float* sb1 = (float*)(smem + OFF_RB1);
    int*   sk1 = (int*)  (smem + OFF_RK1);
    float* sb2 = (float*)(smem + OFF_RB2);
    if (tg == 0) {
#pragma unroll
        for (int s = 0; s < 4; ++s) {
            int row = wm * 32 + (s >> 1) * 16 + (s & 1) * 8 + g;
            sb1[row * 2 + wn] = bs1[s];
            sk1[row * 2 + wn] = bk1[s];
            sb2[row * 2 + wn] = bs2[s];
        }
    }
    __syncthreads();
    if (tid < TMm) {
        float b1 = sb1[tid * 2], b2 = sb2[tid * 2];
        int   k1 = sk1[tid * 2];
        merge2(b1, k1, b2, sb1[tid * 2 + 1], sk1[tid * 2 + 1], sb2[tid * 2 + 1]);
        int row = r0 + tid;
        g_bestk[row] = k1;
        if (b2 - b1 < DELTA) {
            int p = atomicAdd(&g_nflag, 1);
            g_flaglist[p] = row;
        }
    }
}

// ---------------- epilogue (float4, measured 31us): gather, quantize, mask, loss ----------------
__global__ __launch_bounds__(256) void epi_k(const float* __restrict__ z,
                                             const void*  __restrict__ mask,
                                             const float* __restrict__ cb,
                                             float* __restrict__ out_q,
                                             float* __restrict__ out_i,
                                             int write_idx) {
    const int tid  = threadIdx.x;
    const int r0   = blockIdx.x * TMm;
    const int rsub = tid >> 6;        // 0..3
    const int f4   = tid & 63;        // float4 lane
    const int mflag = g_mflag;
    float lsum = 0.f;
#pragma unroll 4
    for (int it = 0; it < 32; ++it) {
        int row = r0 + it * 4 + rsub;
        int k   = g_bestk[row];
        const float4 z4 = __ldg((const float4*)(z  + (size_t)row * Dd + f4 * 4));
        const float4 e4 = __ldg((const float4*)(cb + (size_t)k   * Dd + f4 * 4));
        float q0 = z4.x + (e4.x - z4.x); float l0 = q0 - z4.x;
        float q1 = z4.y + (e4.y - z4.y); float l1 = q1 - z4.y;
        float q2 = z4.z + (e4.z - z4.z); float l2 = q2 - z4.z;
        float q3 = z4.w + (e4.w - z4.w); float l3 = q3 - z4.w;
        lsum = fmaf(l0, l0, lsum); lsum = fmaf(l1, l1, lsum);
        lsum = fmaf(l2, l2, lsum); lsum = fmaf(l3, l3, lsum);
        int mk = read_mask(mask, row, mflag);
        float4 o = mk ? make_float4(q0, q1, q2, q3) : make_float4(0.f, 0.f, 0.f, 0.f);
        *(float4*)(out_q + (size_t)row * Dd + f4 * 4) = o;
    }
    if (write_idx && tid < TMm) {
        int row = r0 + tid;
        int mk  = read_mask(mask, row, mflag);
        out_i[row] = mk ? (float)g_bestk[row] : -1.0f;
    }
#pragma unroll
    for (int off = 16; off > 0; off >>= 1)
        lsum += __shfl_down_sync(0xFFFFFFFFu, lsum, off);
    __shared__ float wsum[8];
    if ((tid & 31) == 0) wsum[tid >> 5] = lsum;
    __syncthreads();
    if (tid == 0) {
        float t = 0.f;
        for (int w = 0; w < 8; ++w) t += wsum[w];
        atomicAdd(&g_loss, (double)t);
    }
}

// ---------------- exact rescue + patch (block per flagged row) ----------------
__global__ __launch_bounds__(256) void rescue_k(const float* __restrict__ z,
                                                const void*  __restrict__ mask,
                                                const float* __restrict__ cb,
                                                float* __restrict__ out_q,
                                                float* __restrict__ out_i,
                                                int write_idx) {
    __shared__ float zs[256];
    __shared__ float sc[256];
    __shared__ int   si[256];
    __shared__ int   s_chg;
    const int tid = threadIdx.x;
    const int nf  = g_nflag;
    const int mflag = g_mflag;
    for (int i = blockIdx.x; i < nf; i += gridDim.x) {
        const int row = g_flaglist[i];
        __syncthreads();
        zs[tid] = z[(size_t)row * Dd + tid];
        __syncthreads();
        float best = 3.4e38f; int bk = 0;
#pragma unroll
        for (int c = 0; c < 2; ++c) {
            int k = tid * 2 + c;
            const float* ck = cb + (size_t)k * Dd;
            float p0 = 0.f, p1 = 0.f, p2 = 0.f, p3 = 0.f;
#pragma unroll 8
            for (int d = 0; d < Dd; d += 4) {
                p0 = fmaf(ck[d],     zs[d],     p0);
                p1 = fmaf(ck[d + 1], zs[d + 1], p1);
                p2 = fmaf(ck[d + 2], zs[d + 2], p2);
                p3 = fmaf(ck[d + 3], zs[d + 3], p3);
            }
            float p = (p0 + p1) + (p2 + p3);
            float s = fmaf(-2.f, p, g_esq[k]);
            if (s < best) { best = s; bk = k; }     // ascending k => lowest-index tie-break
        }
        sc[tid] = best; si[tid] = bk;
        __syncthreads();
        for (int off = 128; off > 0; off >>= 1) {
            if (tid < off) {
                float o = sc[tid + off]; int ok = si[tid + off];
                if (o < sc[tid] || (o == sc[tid] && ok < si[tid])) { sc[tid] = o; si[tid] = ok; }
            }
            __syncthreads();
        }
        const int newk = si[0];
        const int oldk = g_bestk[row];
        if (tid == 0) s_chg = (newk != oldk);
        __syncthreads();
        if (s_chg) {
            int mk = read_mask(mask, row, mflag);
            float zv = zs[tid];
            float en = __ldg(&cb[(size_t)newk * Dd + tid]);
            float eo = __ldg(&cb[(size_t)oldk * Dd + tid]);
            float qn = zv + (en - zv);
            float qo = zv + (eo - zv);
            float ln = qn - zv, lo = qo - zv;
            out_q[(size_t)row * Dd + tid] = mk ? qn : 0.f;
            sc[tid] = ln * ln - lo * lo;
            __syncthreads();
            for (int off = 128; off > 0; off >>= 1) {
                if (tid < off) sc[tid] += sc[tid + off];
                __syncthreads();
            }
            if (tid == 0) {
                atomicAdd(&g_loss, (double)sc[0]);
                if (write_idx) out_i[row] = mk ? (float)newk : -1.0f;
                g_bestk[row] = newk;
            }
        }
    }
}

// ---------------- finalize loss + reset globals for next replay ----------------
__global__ void reset_k(float* out_loss, int need_full) {
    if (need_full)
        out_loss[0] = (float)(0.25 * g_loss / (double)((size_t)ROWS * Dd));
    g_loss  = 0.0;
    g_mflag = 0;
    g_nflag = 0;
}

// ---------------- launch ----------------
extern "C" void kernel_launch(void* const* d_in, const int* in_sizes, int n_in,
                              void* d_out, int out_size) {
    const float* z    = (const float*)d_in[0];
    const void*  mask = d_in[1];
    const float* cb   = (const float*)d_in[2];

    float* out   = (float*)d_out;
    float* out_q = out;
    float* out_i = out + (size_t)ROWS * Dd;
    float* out_l = out_i + ROWS;

    const int need_full = (out_size >= (int)((size_t)ROWS * Dd + ROWS + 1));

    cudaFuncSetAttribute(vq_mma, cudaFuncAttributeMaxDynamicSharedMemorySize, SMEM_SZ);

    detect_k<<<16, 256>>>((const unsigned int*)mask);              // idx 0
    prep_cb<<<64, 256>>>(cb);                                      // idx 1
    prep_z<<<8192, 256>>>(z);                                      // idx 2
    vq_mma<<<NBLK, 256, SMEM_SZ>>>();                              // idx 3 <- ncu samples here
    epi_k<<<NBLK, 256>>>(z, mask, cb, out_q, out_i, need_full);    // idx 4
    rescue_k<<<2048, 256>>>(z, mask, cb, out_q, out_i, need_full); // idx 5
    reset_k<<<1, 1>>>(out_l, need_full);                           // idx 6
}

// round 16
// speedup vs baseline: 2.7593x; 2.7593x over previous
#include <cuda_runtime.h>
#include <cuda_bf16.h>
#include <cstdint>
#include <cstddef>

// Problem constants
#define Bb   16
#define Nn   4096
#define Dd   256
#define Kk   512
#define ROWS (Bb * Nn)        // 65536
#define TMm  128              // rows per MMA CTA
#define NBLK (ROWS / TMm)     // 512
#define DELTA 0.05f

// smem layout (bytes): A-hi 4x16KB tiles, A-lo, B-hi chunk, B-lo chunk, esq, reduce
#define OFF_AH  0
#define OFF_AL  (64 * 1024)
#define OFF_BH  (128 * 1024)
#define OFF_BL  (144 * 1024)
#define OFF_ESQ (160 * 1024)   // 512 floats
#define OFF_RB1 (162 * 1024)   // float sb1[128][2]
#define OFF_RK1 (163 * 1024)   // int   sk1[128][2]
#define OFF_RB2 (164 * 1024)   // float sb2[128][2]
#define SMEM_SZ (165 * 1024)

// ---------------- device globals (scratch; no allocations allowed) ----------------
__device__ double g_loss;
__device__ int    g_mflag;
__device__ int    g_nflag;
__device__ float  g_esq[Kk];
__device__ int    g_bestk[ROWS];
__device__ int    g_flaglist[ROWS];
__device__ uint4  g_cbh4[Kk * Dd / 8];   // codebook hi bf16 [code][dim/8] (256KB)
__device__ uint4  g_cbl4[Kk * Dd / 8];   // codebook lo bf16 (256KB)

// ---------------- helpers ----------------
__device__ __forceinline__ uint32_t smem_u32(const void* p) {
    uint32_t a;
    asm("{ .reg .u64 t; cvta.to.shared.u64 t, %1; cvt.u32.u64 %0, t; }" : "=r"(a) : "l"(p));
    return a;
}

#define LDSM4(r, addr)                                                              \
    asm volatile("ldmatrix.sync.aligned.m8n8.x4.shared.b16 {%0,%1,%2,%3}, [%4];"    \
        : "=r"((r)[0]), "=r"((r)[1]), "=r"((r)[2]), "=r"((r)[3]) : "r"(addr))

#define MMA16816(c, a, b0, b1)                                                      \
    asm volatile("mma.sync.aligned.m16n8k16.row.col.f32.bf16.bf16.f32 "             \
        "{%0,%1,%2,%3}, {%4,%5,%6,%7}, {%8,%9}, {%0,%1,%2,%3};"                     \
        : "+f"((c)[0]), "+f"((c)[1]), "+f"((c)[2]), "+f"((c)[3])                    \
        : "r"((a)[0]), "r"((a)[1]), "r"((a)[2]), "r"((a)[3]), "r"(b0), "r"(b1))

// bf16 split-pack: 8 floats -> hi uint4 + lo uint4
__device__ __forceinline__ void split8(const float* v, uint4& h, uint4& l) {
    uint32_t hw[4], lw[4];
#pragma unroll
    for (int j = 0; j < 4; ++j) {
        __nv_bfloat16 h0 = __float2bfloat16(v[2 * j]);
        __nv_bfloat16 h1 = __float2bfloat16(v[2 * j + 1]);
        float l0 = v[2 * j]     - __bfloat162float(h0);
        float l1 = v[2 * j + 1] - __bfloat162float(h1);
        __nv_bfloat16 g0 = __float2bfloat16(l0);
        __nv_bfloat16 g1 = __float2bfloat16(l1);
        hw[j] = ((uint32_t)__bfloat16_as_ushort(h1) << 16) | __bfloat16_as_ushort(h0);
        lw[j] = ((uint32_t)__bfloat16_as_ushort(g1) << 16) | __bfloat16_as_ushort(g0);
    }
    h = make_uint4(hw[0], hw[1], hw[2], hw[3]);
    l = make_uint4(lw[0], lw[1], lw[2], lw[3]);
}

// merge (b1,k1,b2) with (ob1,ok1,ob2); argmin tie-break = lowest index
__device__ __forceinline__ void merge2(float& b1, int& k1, float& b2,
                                       float ob1, int ok1, float ob2) {
    float lose;
    if (ob1 < b1 || (ob1 == b1 && ok1 < k1)) { lose = b1; b1 = ob1; k1 = ok1; }
    else lose = ob1;
    b2 = fminf(b2, fminf(ob2, lose));
}

// ---------------- prologue kernels ----------------
__global__ void init_k() { g_loss = 0.0; g_mflag = 0; g_nflag = 0; }

__global__ void detect_k(const unsigned int* __restrict__ m) {
    int i = blockIdx.x * blockDim.x + threadIdx.x;
    int flags = 0;
    for (int idx = i; idx < (ROWS / 4); idx += gridDim.x * blockDim.x) {
        unsigned int v = m[idx];
        if (v == 0x3F800000u) flags |= 2;
        else if (v > 1u)      flags |= 1;
    }
    if (flags) atomicOr(&g_mflag, flags);
}

__global__ void prep_cbhl(const float* __restrict__ cb) {
    int code = blockIdx.x;
    int t    = threadIdx.x;         // 0..31, 8 dims each
    float v[8];
    const float* p = cb + (size_t)code * Dd + t * 8;
#pragma unroll
    for (int j = 0; j < 8; ++j) v[j] = p[j];
    uint4 h, l;
    split8(v, h, l);
    g_cbh4[code * 32 + t] = h;
    g_cbl4[code * 32 + t] = l;
}

__global__ void esq_k(const float* __restrict__ cb) {
    int w    = (blockIdx.x * blockDim.x + threadIdx.x) >> 5;
    int lane = threadIdx.x & 31;
    const float* p = cb + (size_t)w * Dd;
    float s = 0.f;
#pragma unroll
    for (int j = 0; j < Dd / 32; ++j) { float v = p[lane + 32 * j]; s = fmaf(v, v, s); }
#pragma unroll
    for (int off = 16; off > 0; off >>= 1) s += __shfl_down_sync(0xFFFFFFFFu, s, off);
    if (lane == 0) g_esq[w] = s;
}

__device__ __forceinline__ int read_mask(const void* m, int n, int flag) {
    if (flag & 2) return ((const float*)m)[n] != 0.0f;
    if (flag & 1) return ((const unsigned char*)m)[n] != 0;
    return ((const int*)m)[n] != 0;
}

// ---------------- main MMA kernel ----------------
// CTA: 128 rows x 512 codes (4 chunks of 128), K=256 (4 d-chunks of 64).
// 8 warps in 4(m) x 2(n) grid; warp tile 32 rows x 64 codes; mma.m16n8k16 bf16.
__global__ __launch_bounds__(256, 1) void vq_mma(const float* __restrict__ z) {
    extern __shared__ char smem[];
    const uint32_t sb = smem_u32(smem);
    const int tid  = threadIdx.x;
    const int lane = tid & 31;
    const int wid  = tid >> 5;
    const int wm   = wid >> 1;         // 0..3
    const int wn   = wid & 1;          // 0..1
    const int g    = lane >> 2;        // 0..7
    const int tg   = lane & 3;         // 0..3
    const int r0   = blockIdx.x * TMm;

    float* esq_s = (float*)(smem + OFF_ESQ);

    // ---- fill A (z hi/lo) once: 4 d-chunk tiles of [128 rows][64 dims] SW128 ----
#pragma unroll 4
    for (int it = 0; it < 16; ++it) {
        int idx = tid + it * 256;          // 0..4095
        int row = idx >> 5;                // 0..127
        int u   = idx & 31;                // uint4-chunk within row (8 dims)
        int dc  = u >> 3;
        int q   = u & 7;
        float v[8];
        const float* p = z + (size_t)(r0 + row) * Dd + u * 8;
        const float4 v0 = *reinterpret_cast<const float4*>(p);
        const float4 v1 = *reinterpret_cast<const float4*>(p + 4);
        v[0] = v0.x; v[1] = v0.y; v[2] = v0.z; v[3] = v0.w;
        v[4] = v1.x; v[5] = v1.y; v[6] = v1.z; v[7] = v1.w;
        uint4 h, l;
        split8(v, h, l);
        uint32_t off = dc * 16384 + row * 128 + ((q * 16) ^ ((row & 7) * 16));
        *reinterpret_cast<uint4*>(smem + OFF_AH + off) = h;
        *reinterpret_cast<uint4*>(smem + OFF_AL + off) = l;
    }
    esq_s[tid]       = g_esq[tid];
    esq_s[tid + 256] = g_esq[tid + 256];

    // ldmatrix per-lane constants
    const int sw      = (lane & 7) * 16;                       // swizzle xor (row&7 == lane&7)
    const int aRowT   = ((lane >> 3) & 1) * 8 + (lane & 7);    // row within 16-row tile
    const int aByteT  = (lane >> 4) * 16;                      // k-byte half
    const int bCodeT  = (lane >> 4) * 8 + (lane & 7);          // code within 16-code pair
    const int bByteT  = ((lane >> 3) & 1) * 16;

    // per-thread running best/second-best for 4 rows
    float bs1[4], bs2[4];
    int   bk1[4];
#pragma unroll
    for (int s = 0; s < 4; ++s) { bs1[s] = 3.4e38f; bs2[s] = 3.4e38f; bk1[s] = 0; }

    for (int kc = 0; kc < 4; ++kc) {               // code chunks of 128
        float acc[2][8][4];
#pragma unroll
        for (int mt = 0; mt < 2; ++mt)
#pragma unroll
            for (int nt = 0; nt < 8; ++nt)
#pragma unroll
                for (int c = 0; c < 4; ++c) acc[mt][nt][c] = 0.f;

        for (int dc = 0; dc < 4; ++dc) {           // d chunks of 64
            __syncthreads();
            // ---- fill B chunk hi/lo: [128 codes][64 dims] SW128 ----
#pragma unroll
            for (int it = 0; it < 4; ++it) {
                int idx  = tid + it * 256;         // 0..1023
                int code = idx >> 3;
                int q    = idx & 7;
                int gi   = (kc * 128 + code) * 32 + dc * 8 + q;
                uint32_t off = code * 128 + ((q * 16) ^ ((code & 7) * 16));
                *reinterpret_cast<uint4*>(smem + OFF_BH + off) = g_cbh4[gi];
                *reinterpret_cast<uint4*>(smem + OFF_BL + off) = g_cbl4[gi];
            }
            __syncthreads();

            const uint32_t aBase = sb + OFF_AH + dc * 16384 +
                                   (uint32_t)((wm * 32 + aRowT) * 128);
            const uint32_t bBase = sb + OFF_BH + (uint32_t)((wn * 64 + bCodeT) * 128);

#pragma unroll
            for (int ks = 0; ks < 4; ++ks) {       // K16 steps
                const uint32_t xa = (uint32_t)((ks * 32 + aByteT) ^ sw);
                const uint32_t xb = (uint32_t)((ks * 32 + bByteT) ^ sw);

                uint32_t ah[2][4], al[2][4];
#pragma unroll
                for (int mt = 0; mt < 2; ++mt) {
                    LDSM4(ah[mt], aBase + mt * (16 * 128) + xa);
                    LDSM4(al[mt], aBase + (OFF_AL - OFF_AH) + mt * (16 * 128) + xa);
                }
                uint32_t bh[4][4], bl[4][4];
#pragma unroll
                for (int np = 0; np < 4; ++np) {
                    LDSM4(bh[np], bBase + np * (16 * 128) + xb);
                    LDSM4(bl[np], bBase + (OFF_BL - OFF_BH) + np * (16 * 128) + xb);
                }
#pragma unroll
                for (int mt = 0; mt < 2; ++mt)
#pragma unroll
                    for (int np = 0; np < 4; ++np) {
                        MMA16816(acc[mt][2 * np],     ah[mt], bh[np][0], bh[np][1]); // hh even
                        MMA16816(acc[mt][2 * np],     ah[mt], bl[np][0], bl[np][1]); // hl
                        MMA16816(acc[mt][2 * np],     al[mt], bh[np][0], bh[np][1]); // lh
                        MMA16816(acc[mt][2 * np + 1], ah[mt], bh[np][2], bh[np][3]); // hh odd
                        MMA16816(acc[mt][2 * np + 1], ah[mt], bl[np][2], bl[np][3]);
                        MMA16816(acc[mt][2 * np + 1], al[mt], bh[np][2], bh[np][3]);
                    }
            }
        }

        // ---- fold chunk into running argmin: score = esq - 2*dot ----
        const int ccbase = kc * 128 + wn * 64;
#pragma unroll
        for (int mt = 0; mt < 2; ++mt)
#pragma unroll
            for (int nt = 0; nt < 8; ++nt)
#pragma unroll
                for (int c = 0; c < 4; ++c) {
                    int code = ccbase + nt * 8 + 2 * tg + (c & 1);
                    int slot = mt * 2 + (c >> 1);
                    float s = fmaf(-2.f, acc[mt][nt][c], esq_s[code]);
                    if (s < bs1[slot]) { bs2[slot] = bs1[slot]; bs1[slot] = s; bk1[slot] = code; }
                    else if (s < bs2[slot]) bs2[slot] = s;
                }
    }

    // ---- quad reduce (lanes sharing a row: tg 0..3) ----
#pragma unroll
    for (int s = 0; s < 4; ++s) {
#pragma unroll
        for (int m = 1; m <= 2; m <<= 1) {
            float ob1 = __shfl_xor_sync(0xFFFFFFFFu, bs1[s], m);
            int   ok1 = __shfl_xor_sync(0xFFFFFFFFu, bk1[s], m);
            float ob2 = __shfl_xor_sync(0xFFFFFFFFu, bs2[s], m);
            merge2(bs1[s], bk1[s], bs2[s], ob1, ok1, ob2);
        }
    }
    __syncthreads();
    float* sb1 = (float*)(smem + OFF_RB1);
    int*   sk1 = (int*)  (smem + OFF_RK1);
    float* sb2 = (float*)(smem + OFF_RB2);
    if (tg == 0) {
#pragma unroll
        for (int s = 0; s < 4; ++s) {
            int row = wm * 32 + (s >> 1) * 16 + (s & 1) * 8 + g;
            sb1[row * 2 + wn] = bs1[s];
            sk1[row * 2 + wn] = bk1[s];
            sb2[row * 2 + wn] = bs2[s];
        }
    }
    __syncthreads();
    if (tid < TMm) {
        float b1 = sb1[tid * 2], b2 = sb2[tid * 2];
        int   k1 = sk1[tid * 2];
        merge2(b1, k1, b2, sb1[tid * 2 + 1], sk1[tid * 2 + 1], sb2[tid * 2 + 1]);
        int row = r0 + tid;
        g_bestk[row] = k1;
        if (b2 - b1 < DELTA) {
            int p = atomicAdd(&g_nflag, 1);
            g_flaglist[p] = row;
        }
    }
}

// ---------------- exact fp32 rescue for near-tie rows ----------------
__global__ __launch_bounds__(256) void vq_exact(const float* __restrict__ z,
                                                const float* __restrict__ cb) {
    const int nf   = g_nflag;
    const int gw   = (blockIdx.x * blockDim.x + threadIdx.x) >> 5;
    const int lane = threadIdx.x & 31;
    const int nw   = (gridDim.x * blockDim.x) >> 5;
    for (int i = gw; i < nf; i += nw) {
        const int row = g_flaglist[i];
        float zr[8];
#pragma unroll
        for (int j = 0; j < 8; ++j) zr[j] = z[(size_t)row * Dd + j * 32 + lane];
        float best = 3.4e38f; int bk = 0;
        for (int k = 0; k < Kk; ++k) {
            const float* ck = cb + (size_t)k * Dd;
            float p = 0.f;
#pragma unroll
            for (int j = 0; j < 8; ++j) p = fmaf(zr[j], ck[j * 32 + lane], p);
#pragma unroll
            for (int off = 16; off > 0; off >>= 1) p += __shfl_xor_sync(0xFFFFFFFFu, p, off);
            float s = fmaf(-2.f, p, g_esq[k]);
            if (s < best) { best = s; bk = k; }
        }
        if (lane == 0) g_bestk[row] = bk;
    }
}

// ---------------- epilogue: gather, quantize, mask, loss ----------------
__global__ __launch_bounds__(256) void epi_k(const float* __restrict__ z,
                                             const void*  __restrict__ mask,
                                             const float* __restrict__ cb,
                                             float* __restrict__ out_q,
                                             float* __restrict__ out_i,
                                             int write_idx) {
    const int tid = threadIdx.x;
    const int r0  = blockIdx.x * TMm;
    const int mflag = g_mflag;
    float lsum = 0.f;
    for (int it = 0; it < TMm; ++it) {
        int row = r0 + it;
        int k   = g_bestk[row];
        float zv = __ldg(&z[(size_t)row * Dd + tid]);
        float e  = __ldg(&cb[(size_t)k * Dd + tid]);
        float d1 = e - zv;
        float q  = zv + d1;
        float lq = q - zv;
        lsum = fmaf(lq, lq, lsum);
        int mk = read_mask(mask, row, mflag);
        out_q[(size_t)row * Dd + tid] = mk ? q : 0.f;
    }
    if (write_idx && tid < TMm) {
        int row = r0 + tid;
        int mk  = read_mask(mask, row, mflag);
        out_i[row] = mk ? (float)g_bestk[row] : -1.0f;
    }
#pragma unroll
    for (int off = 16; off > 0; off >>= 1)
        lsum += __shfl_down_sync(0xFFFFFFFFu, lsum, off);
    __shared__ float wsum[8];
    if ((tid & 31) == 0) wsum[tid >> 5] = lsum;
    __syncthreads();
    if (tid == 0) {
        float t = 0.f;
        for (int w = 0; w < 8; ++w) t += wsum[w];
        atomicAdd(&g_loss, (double)t);
    }
}

__global__ void fin_k(float* out_loss) {
    out_loss[0] = (float)(0.25 * g_loss / (double)((size_t)ROWS * Dd));
}

// ---------------- launch ----------------
extern "C" void kernel_launch(void* const* d_in, const int* in_sizes, int n_in,
                              void* d_out, int out_size) {
    const float* z    = (const float*)d_in[0];
    const void*  mask = d_in[1];
    const float* cb   = (const float*)d_in[2];

    float* out   = (float*)d_out;
    float* out_q = out;
    float* out_i = out + (size_t)ROWS * Dd;
    float* out_l = out_i + ROWS;

    const int need_full = (out_size >= (int)((size_t)ROWS * Dd + ROWS + 1));

    cudaFuncSetAttribute(vq_mma, cudaFuncAttributeMaxDynamicSharedMemorySize, SMEM_SZ);

    init_k<<<1, 1>>>();
    detect_k<<<16, 256>>>((const unsigned int*)mask);
    prep_cbhl<<<Kk, 32>>>(cb);
    esq_k<<<64, 256>>>(cb);
    vq_mma<<<NBLK, 256, SMEM_SZ>>>(z);
    vq_exact<<<128, 256>>>(z, cb);
    epi_k<<<NBLK, 256>>>(z, mask, cb, out_q, out_i, need_full);
    if (need_full) fin_k<<<1, 1>>>(out_l);
}